// round 13
// baseline (speedup 1.0000x reference)
#include <cuda_runtime.h>
#include <cstdint>

#define BSZ  8
#define CDIM 64
#define NPTS 4096
#define KNN  20
#define OC   64
#define QT   64          // queries per block in k_knn

// ---------------- scratch (device globals; no allocation) ----------------
__device__ float g_sq [BSZ*NPTS];     // NEGATED squared norms: -|x|^2
__device__ float g_u  [BSZ*NPTS*OC];
__device__ float g_v  [BSZ*NPTS*OC];
__device__ int   g_idx[BSZ*NPTS*KNN];
__device__ float g_mxv[BSZ*NPTS*OC];
__device__ float g_mnv[BSZ*NPTS*OC];
__device__ float g_S1[OC];
__device__ float g_S2[OC];
__device__ float g_ga[OC];
__device__ float g_gb[OC];

// packed fp32x2 helpers (FFMA2 only reachable via PTX)
#define FMA2(acc, a, b) \
    asm("fma.rn.f32x2 %0, %1, %2, %0;" : "+l"(acc) : "l"(a), "l"(b))
#define FMA2O(d, a, b, c) \
    asm("fma.rn.f32x2 %0, %1, %2, %3;" : "=l"(d) : "l"(a), "l"(b), "l"(c))
#define DUP2(dst, f) \
    asm("mov.b64 %0, {%1, %1};" : "=l"(dst) : "f"(f))
#define STS2x64(addr, v0, v1) \
    asm volatile("st.shared.v2.u64 [%0], {%1, %2};" \
                 :: "r"(addr), "l"(v0), "l"(v1) : "memory")

__device__ __forceinline__ uint32_t smem_u32(const void* p) {
    uint32_t a;
    asm("{ .reg .u64 t; cvta.to.shared.u64 t, %1; cvt.u32.u64 %0, t; }"
        : "=r"(a) : "l"(p));
    return a;
}

// ---------------- kernel 0: NEGATED squared norms ----------------
__global__ __launch_bounds__(256) void k_sq(const float* __restrict__ x) {
    const int b = blockIdx.y;
    const int n = blockIdx.x * 256 + threadIdx.x;
    const float* xb = x + (size_t)b * CDIM * NPTS;
    float s = 0.f;
#pragma unroll 8
    for (int c = 0; c < CDIM; ++c) {
        float t = xb[c * NPTS + n];
        s += t * t;
    }
    g_sq[b * NPTS + n] = -s;
}

// ---------------- kernel Z: zero stats (pads launch order so ncu's
// fixed capture slot lands on k_knn) ----------------
__global__ void k_zstat() {
    if (threadIdx.x < OC) {
        g_S1[threadIdx.x] = 0.f;
        g_S2[threadIdx.x] = 0.f;
    }
}

// ---------------- kernel A: u = W1*x, v = (W2-W1)*x, layout [b][n][o] ---
__global__ __launch_bounds__(256) void k_uv(const float* __restrict__ x,
                                            const float* __restrict__ W) {
    __shared__ float Wc[128 * 64];
    __shared__ float xt[64 * 32];
    const int b = blockIdx.y, n0 = blockIdx.x * 32;
    const int tx = threadIdx.x, ty = threadIdx.y, tid = ty * 16 + tx;

    for (int i = tid; i < 128 * 64; i += 256) {
        int r = i >> 6, c = i & 63;
        float wv;
        if (r < 64) wv = W[r * 128 + c];
        else        wv = W[(r - 64) * 128 + 64 + c] - W[(r - 64) * 128 + c];
        Wc[i] = wv;
    }
    const float* xb = x + (size_t)b * CDIM * NPTS;
    for (int i = tid; i < 64 * 32; i += 256) {
        int c = i >> 5, nn = i & 31;
        xt[i] = xb[c * NPTS + n0 + nn];
    }
    __syncthreads();

    float acc[8][2] = {};
#pragma unroll 8
    for (int c = 0; c < 64; ++c) {
        float2 bv = *(const float2*)&xt[c * 32 + tx * 2];
#pragma unroll
        for (int i = 0; i < 8; ++i) {
            float a = Wc[(ty * 8 + i) * 64 + c];
            acc[i][0] += a * bv.x;
            acc[i][1] += a * bv.y;
        }
    }
    __syncthreads();

    if (ty < 8) {
#pragma unroll
        for (int i = 0; i < 8; ++i) {
            Wc[(tx * 2 + 0) * 65 + ty * 8 + i] = acc[i][0];
            Wc[(tx * 2 + 1) * 65 + ty * 8 + i] = acc[i][1];
        }
    }
    __syncthreads();
    {
        float* dst = g_u + ((size_t)b * NPTS + n0) * OC;
        for (int i = tid; i < 32 * 64; i += 256) {
            int nn = i >> 6, oo = i & 63;
            dst[i] = Wc[nn * 65 + oo];
        }
    }
    __syncthreads();
    if (ty >= 8) {
#pragma unroll
        for (int i = 0; i < 8; ++i) {
            Wc[(tx * 2 + 0) * 65 + (ty - 8) * 8 + i] = acc[i][0];
            Wc[(tx * 2 + 1) * 65 + (ty - 8) * 8 + i] = acc[i][1];
        }
    }
    __syncthreads();
    {
        float* dst = g_v + ((size_t)b * NPTS + n0) * OC;
        for (int i = tid; i < 32 * 64; i += 256) {
            int nn = i >> 6, oo = i & 63;
            dst[i] = Wc[nn * 65 + oo];
        }
    }
}

// ---------------- kernel B: FFMA2 Gram, MOV-free inner loop -------------
// Thread microtile: 2 rows x 8 cols. tx = tid&7 (colgroup of 8),
// ty = tid>>3 (rowpair). Warp = 4 ty values x 8 tx -> rows 8w..8w+7 full.
//
// smem (floats):
//   qsdup[64c][128]   : each query value duplicated -> A is packed {a,a}
//   Bs[2][BSIZE]      : skewed per-colgroup: addr g*BSTRIDE + c*8 + j
//   keys[64][68]
//   negsq[2][64]
#define BSTRIDE 524      // 64*8 + 12: per-warp banks tx*12 mod 32 all distinct
#define BSIZE   4192     // 7*524 + 512, padded
#define KPAD    68
#define SM_QS   0
#define SM_BS   8192
#define SM_KEYS (SM_BS + 2 * BSIZE)
#define SM_NSQ  (SM_KEYS + 64 * KPAD)
#define SM_FLOATS (SM_NSQ + 2 * 64)
#define SM_BYTES  (SM_FLOATS * 4)

__device__ __forceinline__ void insert_cand(float k, int m, float& tk, int& ti,
                                            float& thr, int& minl, int lane) {
    unsigned bal = __ballot_sync(0xffffffffu, k > thr);
    while (bal) {
        int src = __ffs(bal) - 1;
        bal &= bal - 1;
        float ck = __shfl_sync(0xffffffffu, k, src);
        int   cm = __shfl_sync(0xffffffffu, m, src);
        if (ck > thr) {                  // re-check: thr may have risen
            if (lane == minl) { tk = ck; ti = cm; }
            float mv = (lane < KNN) ? tk : 3.4e38f;
            int   ml = lane;
#pragma unroll
            for (int off = 16; off; off >>= 1) {
                float ov = __shfl_xor_sync(0xffffffffu, mv, off);
                int   ol = __shfl_xor_sync(0xffffffffu, ml, off);
                if (ov < mv || (ov == mv && ol < ml)) { mv = ov; ml = ol; }
            }
            thr = mv; minl = ml;         // uniform across warp
        }
    }
}

extern __shared__ float sm[];

__global__ __launch_bounds__(256, 2) void k_knn(const float* __restrict__ x) {
    float* qsdup = sm + SM_QS;
    float* BsA   = sm + SM_BS;
    float* keys  = sm + SM_KEYS;
    float* nsqA  = sm + SM_NSQ;

    const int b  = blockIdx.y;
    const int q0 = blockIdx.x * QT;
    const int tid  = threadIdx.x;
    const int tx   = tid & 7;           // colgroup: 8 candidate cols
    const int ty   = tid >> 3;          // rowpair: rows 2ty, 2ty+1
    const int lane = tid & 31, warp = tid >> 5;   // 8 warps, 8 rows each
    const float* xb = x + (size_t)b * CDIM * NPTS;

    // ---- prologue: qsdup + B tile 0 (skewed) + negsq[0] ----
    for (int i = tid; i < 64 * 64; i += 256) {
        int c = i >> 6, q = i & 63;
        float v = xb[c * NPTS + q0 + q];
        qsdup[c * 128 + 2 * q]     = v;
        qsdup[c * 128 + 2 * q + 1] = v;
    }
    for (int i = tid; i < 64 * 64; i += 256) {
        int c = i >> 6, m = i & 63;
        BsA[(m >> 3) * BSTRIDE + c * 8 + (m & 7)] = xb[c * NPTS + m];
    }
    if (tid < 64) nsqA[tid] = g_sq[b * NPTS + tid];

    float tk[8], thr[8];
    int   ti[8], minl[8];
#pragma unroll
    for (int r = 0; r < 8; ++r) {
        tk[r] = -3.4e38f; ti[r] = 0; thr[r] = -3.4e38f; minl[r] = 0;
    }
    __syncthreads();

    const uint32_t smb = smem_u32(sm);
    const uint32_t aAddr = smb + (SM_QS + 4 * ty) * 4;               // + c*512B
    const uint32_t bAddr0 = smb + (SM_BS + tx * BSTRIDE) * 4;        // + cur*BSIZE*4 + c*32B
    const uint32_t kAddr = smb + (SM_KEYS + (2 * ty) * KPAD + 8 * tx) * 4;

    unsigned long long two_dup;
    DUP2(two_dup, 2.0f);

    for (int t = 0; t < NPTS / 64; ++t) {
        const int cur = t & 1;
        const int m0 = t * 64;
        const uint32_t bAddr = bAddr0 + (uint32_t)cur * (BSIZE * 4);

        // ---- stage next B tile + negsq into registers ----
        float4 stg[4];
        float nsqstg = 0.f;
        if (t + 1 < NPTS / 64) {
            const int m0n = m0 + 64;
#pragma unroll
            for (int s = 0; s < 4; ++s) {
                int i4 = tid + s * 256;
                stg[s] = *(const float4*)&xb[(i4 >> 4) * NPTS + m0n + (i4 & 15) * 4];
            }
            if (tid < 64) nsqstg = g_sq[b * NPTS + m0n + tid];
        }

        // ---- MOV-free FFMA2 loop: 2 rows x 4 colpairs ----
        unsigned long long acc[2][4];
#pragma unroll
        for (int i = 0; i < 2; ++i)
#pragma unroll
            for (int j = 0; j < 4; ++j) acc[i][j] = 0ull;

#pragma unroll 8
        for (int c = 0; c < 64; ++c) {
            ulonglong2 A;   // {row 2ty dup, row 2ty+1 dup}
            asm volatile("ld.shared.v2.u64 {%0,%1}, [%2];"
                         : "=l"(A.x), "=l"(A.y) : "r"(aAddr + c * 512));
            ulonglong2 B0, B1;   // col pairs {8tx..+3}, {8tx+4..+7}
            asm volatile("ld.shared.v2.u64 {%0,%1}, [%2];"
                         : "=l"(B0.x), "=l"(B0.y) : "r"(bAddr + c * 32));
            asm volatile("ld.shared.v2.u64 {%0,%1}, [%2];"
                         : "=l"(B1.x), "=l"(B1.y) : "r"(bAddr + c * 32 + 16));
            FMA2(acc[0][0], A.x, B0.x); FMA2(acc[0][1], A.x, B0.y);
            FMA2(acc[0][2], A.x, B1.x); FMA2(acc[0][3], A.x, B1.y);
            FMA2(acc[1][0], A.y, B0.x); FMA2(acc[1][1], A.y, B0.y);
            FMA2(acc[1][2], A.y, B1.x); FMA2(acc[1][3], A.y, B1.y);
        }

        // ---- epilogue: keys = 2*dot + negsq (packed), store to keys smem
        {
            const uint32_t nbase = smb + (SM_NSQ + cur * 64 + 8 * tx) * 4;
            ulonglong2 n0, n1;
            asm volatile("ld.shared.v2.u64 {%0,%1}, [%2];"
                         : "=l"(n0.x), "=l"(n0.y) : "r"(nbase));
            asm volatile("ld.shared.v2.u64 {%0,%1}, [%2];"
                         : "=l"(n1.x), "=l"(n1.y) : "r"(nbase + 16));
#pragma unroll
            for (int r = 0; r < 2; ++r) {
                unsigned long long k0, k1, k2, k3;
                FMA2O(k0, acc[r][0], two_dup, n0.x);
                FMA2O(k1, acc[r][1], two_dup, n0.y);
                FMA2O(k2, acc[r][2], two_dup, n1.x);
                FMA2O(k3, acc[r][3], two_dup, n1.y);
                STS2x64(kAddr + r * (KPAD * 4), k0, k1);
                STS2x64(kAddr + r * (KPAD * 4) + 16, k2, k3);
            }
        }
        __syncwarp();     // keys rows 8w..8w+7 visible within warp

        // ---- selection: warp-private keys rows, pure LDS + ballot ----
#pragma unroll
        for (int r = 0; r < 8; ++r) {
            const float* krow = &keys[(warp * 8 + r) * KPAD];
            float k0 = krow[lane];
            float k1 = krow[32 + lane];
            insert_cand(k0, m0 + lane,      tk[r], ti[r], thr[r], minl[r], lane);
            insert_cand(k1, m0 + 32 + lane, tk[r], ti[r], thr[r], minl[r], lane);
        }

        // ---- commit staged tile to the other buffer (skewed) ----
        if (t + 1 < NPTS / 64) {
            float* Bn = BsA + (cur ^ 1) * BSIZE;
#pragma unroll
            for (int s = 0; s < 4; ++s) {
                int i4 = tid + s * 256;
                int c = i4 >> 4, mst = (i4 & 15) * 4;
                *(float4*)&Bn[(mst >> 3) * BSTRIDE + c * 8 + (mst & 7)] = stg[s];
            }
            if (tid < 64) nsqA[(cur ^ 1) * 64 + tid] = nsqstg;
        }
        __syncthreads();  // next Bs/negsq ready; cur fully consumed
    }

    if (lane < KNN) {
#pragma unroll
        for (int r = 0; r < 8; ++r)
            g_idx[((size_t)b * NPTS + q0 + warp * 8 + r) * KNN + lane] = ti[r];
    }
}

// ---------------- kernel C: one gather pass: max/min + BN stats ----------
__global__ __launch_bounds__(256) void k_gather() {
    __shared__ int   sidx[4][KNN];
    __shared__ float red[2][4][64];
    const int o = threadIdx.x;
    const int py = threadIdx.y;
    const int tid = py * 64 + o;
    const int b = blockIdx.y;
    const int n0 = blockIdx.x * 64;
    const float* ub = g_u + (size_t)b * NPTS * OC;
    float s1 = 0.f, s2 = 0.f;

    for (int it = 0; it < 16; ++it) {
        __syncthreads();
        if (tid < 4 * KNN) {
            int g = tid / KNN, j = tid % KNN;
            sidx[g][j] = g_idx[((size_t)b * NPTS + n0 + it * 4 + g) * KNN + j];
        }
        __syncthreads();
        const int n = n0 + it * 4 + py;
        float s = 0.f, q = 0.f, mx = -3.4e38f, mn = 3.4e38f;
#pragma unroll
        for (int j = 0; j < KNN; ++j) {
            float val = ub[(size_t)sidx[py][j] * OC + o];
            s += val; q += val * val;
            mx = fmaxf(mx, val); mn = fminf(mn, val);
        }
        const size_t off = ((size_t)b * NPTS + n) * OC + o;
        float vv = g_v[off];
        g_mxv[off] = mx + vv;
        g_mnv[off] = mn + vv;
        s1 += (float)KNN * vv + s;
        s2 += (float)KNN * vv * vv + 2.f * vv * s + q;
    }
    red[0][py][o] = s1;
    red[1][py][o] = s2;
    __syncthreads();
    if (py == 0) {
        float a = red[0][0][o] + red[0][1][o] + red[0][2][o] + red[0][3][o];
        float c = red[1][0][o] + red[1][1][o] + red[1][2][o] + red[1][3][o];
        atomicAdd(&g_S1[o], a);
        atomicAdd(&g_S2[o], c);
    }
}

// ---------------- kernel D: finalize BN affine coefficients --------------
__global__ void k_finalize(const float* __restrict__ gamma,
                           const float* __restrict__ beta) {
    int o = threadIdx.x;
    const float M = (float)BSZ * (float)NPTS * (float)KNN;
    float mean = g_S1[o] / M;
    float var  = g_S2[o] / M - mean * mean;
    float a = gamma[o] * rsqrtf(var + 1e-5f);
    g_ga[o] = a;
    g_gb[o] = beta[o] - mean * a;
}

// ---------------- kernel E: affine + LeakyReLU + transpose to [b][o][n] --
__global__ __launch_bounds__(256) void k_out(float* __restrict__ out) {
    __shared__ float tile[64][65];
    const int o = threadIdx.x, ty = threadIdx.y;
    const int b = blockIdx.y, n0 = blockIdx.x * 64;
    const float a = g_ga[o], bc = g_gb[o];
#pragma unroll
    for (int it = 0; it < 16; ++it) {
        int nl = it * 4 + ty;
        size_t off = ((size_t)b * NPTS + n0 + nl) * OC + o;
        float raw = (a >= 0.f) ? g_mxv[off] : g_mnv[off];
        float val = fmaf(a, raw, bc);
        tile[nl][o] = (val >= 0.f) ? val : 0.2f * val;
    }
    __syncthreads();
#pragma unroll
    for (int it = 0; it < 16; ++it) {
        int oo = it * 4 + ty;
        out[((size_t)b * OC + oo) * NPTS + n0 + o] = tile[o][oo];
    }
}

// ---------------- launch ----------------
extern "C" void kernel_launch(void* const* d_in, const int* in_sizes, int n_in,
                              void* d_out, int out_size) {
    const float* x     = (const float*)d_in[0];
    const float* W     = (const float*)d_in[1];
    const float* gamma = (const float*)d_in[2];
    const float* beta  = (const float*)d_in[3];
    float* out = (float*)d_out;

    cudaFuncSetAttribute(k_knn, cudaFuncAttributeMaxDynamicSharedMemorySize,
                         SM_BYTES);

    k_sq      <<<dim3(NPTS / 256, BSZ), 256>>>(x);
    k_uv      <<<dim3(NPTS / 32,  BSZ), dim3(16, 16)>>>(x, W);
    k_zstat   <<<1, 64>>>();                        // pads slot 3 -> k_knn profiled
    k_knn     <<<dim3(NPTS / QT,  BSZ), 256, SM_BYTES>>>(x);
    k_gather  <<<dim3(NPTS / 64,  BSZ), dim3(64, 4)>>>();
    k_finalize<<<1, 64>>>(gamma, beta);
    k_out     <<<dim3(NPTS / 64,  BSZ), dim3(64, 4)>>>(out);
}

// round 14
// speedup vs baseline: 1.1824x; 1.1824x over previous
#include <cuda_runtime.h>
#include <cstdint>

#define BSZ  8
#define CDIM 64
#define NPTS 4096
#define KNN  20
#define OC   64
#define QT   64          // queries per block in k_knn

// ---------------- scratch (device globals; no allocation) ----------------
__device__ float g_sq [BSZ*NPTS];     // NEGATED squared norms: -|x|^2
__device__ float g_u  [BSZ*NPTS*OC];
__device__ float g_v  [BSZ*NPTS*OC];
__device__ int   g_idx[BSZ*NPTS*KNN];
__device__ float g_mxv[BSZ*NPTS*OC];
__device__ float g_mnv[BSZ*NPTS*OC];
__device__ float g_S1[OC];
__device__ float g_S2[OC];
__device__ float g_ga[OC];
__device__ float g_gb[OC];

// packed fp32x2 helpers (FFMA2 only reachable via PTX)
#define FMA2(acc, a, b) \
    asm("fma.rn.f32x2 %0, %1, %2, %0;" : "+l"(acc) : "l"(a), "l"(b))
#define DUP2(dst, f) \
    asm("mov.b64 %0, {%1, %1};" : "=l"(dst) : "f"(f))
#define UNPK2(lo, hi, src) \
    asm("mov.b64 {%0, %1}, %2;" : "=f"(lo), "=f"(hi) : "l"(src))

__device__ __forceinline__ uint32_t smem_u32(const void* p) {
    uint32_t a;
    asm("{ .reg .u64 t; cvta.to.shared.u64 t, %1; cvt.u32.u64 %0, t; }"
        : "=r"(a) : "l"(p));
    return a;
}

// ---------------- kernel 0: NEGATED squared norms ----------------
__global__ __launch_bounds__(256) void k_sq(const float* __restrict__ x) {
    const int b = blockIdx.y;
    const int n = blockIdx.x * 256 + threadIdx.x;
    const float* xb = x + (size_t)b * CDIM * NPTS;
    float s = 0.f;
#pragma unroll 8
    for (int c = 0; c < CDIM; ++c) {
        float t = xb[c * NPTS + n];
        s += t * t;
    }
    g_sq[b * NPTS + n] = -s;
}

// ---------------- kernel Z: zero stats (pads launch order so ncu's
// fixed capture slot lands on k_knn) ----------------
__global__ void k_zstat() {
    if (threadIdx.x < OC) {
        g_S1[threadIdx.x] = 0.f;
        g_S2[threadIdx.x] = 0.f;
    }
}

// ---------------- kernel A: u = W1*x, v = (W2-W1)*x, layout [b][n][o] ---
__global__ __launch_bounds__(256) void k_uv(const float* __restrict__ x,
                                            const float* __restrict__ W) {
    __shared__ float Wc[128 * 64];
    __shared__ float xt[64 * 32];
    const int b = blockIdx.y, n0 = blockIdx.x * 32;
    const int tx = threadIdx.x, ty = threadIdx.y, tid = ty * 16 + tx;

    for (int i = tid; i < 128 * 64; i += 256) {
        int r = i >> 6, c = i & 63;
        float wv;
        if (r < 64) wv = W[r * 128 + c];
        else        wv = W[(r - 64) * 128 + 64 + c] - W[(r - 64) * 128 + c];
        Wc[i] = wv;
    }
    const float* xb = x + (size_t)b * CDIM * NPTS;
    for (int i = tid; i < 64 * 32; i += 256) {
        int c = i >> 5, nn = i & 31;
        xt[i] = xb[c * NPTS + n0 + nn];
    }
    __syncthreads();

    float acc[8][2] = {};
#pragma unroll 8
    for (int c = 0; c < 64; ++c) {
        float2 bv = *(const float2*)&xt[c * 32 + tx * 2];
#pragma unroll
        for (int i = 0; i < 8; ++i) {
            float a = Wc[(ty * 8 + i) * 64 + c];
            acc[i][0] += a * bv.x;
            acc[i][1] += a * bv.y;
        }
    }
    __syncthreads();

    if (ty < 8) {
#pragma unroll
        for (int i = 0; i < 8; ++i) {
            Wc[(tx * 2 + 0) * 65 + ty * 8 + i] = acc[i][0];
            Wc[(tx * 2 + 1) * 65 + ty * 8 + i] = acc[i][1];
        }
    }
    __syncthreads();
    {
        float* dst = g_u + ((size_t)b * NPTS + n0) * OC;
        for (int i = tid; i < 32 * 64; i += 256) {
            int nn = i >> 6, oo = i & 63;
            dst[i] = Wc[nn * 65 + oo];
        }
    }
    __syncthreads();
    if (ty >= 8) {
#pragma unroll
        for (int i = 0; i < 8; ++i) {
            Wc[(tx * 2 + 0) * 65 + (ty - 8) * 8 + i] = acc[i][0];
            Wc[(tx * 2 + 1) * 65 + (ty - 8) * 8 + i] = acc[i][1];
        }
    }
    __syncthreads();
    {
        float* dst = g_v + ((size_t)b * NPTS + n0) * OC;
        for (int i = tid; i < 32 * 64; i += 256) {
            int nn = i >> 6, oo = i & 63;
            dst[i] = Wc[nn * 65 + oo];
        }
    }
}

// ---------------- kernel B: FFMA2 Gram with broadcast-A -----------------
// 256 threads = 8 warps. Warp w owns query rows 8w..8w+7 (A smem address
// is warp-uniform -> LDS broadcast, ~free crossbar). Lane owns candidate
// cols {2*lane, 2*lane+1}. Microtile 8 rows x 2 cols = acc[4][2] packed.
//
// smem (floats): qs[64c][64q] | Bs[64c][64m] | keys[64][68] | nsq[64]
#define KPAD  68
#define SM_QS   0
#define SM_BS   (64 * 64)
#define SM_KEYS (SM_BS + 64 * 64)
#define SM_NSQ  (SM_KEYS + 64 * KPAD)
#define SM_FLOATS (SM_NSQ + 64)
#define SM_BYTES  (SM_FLOATS * 4)

__device__ __forceinline__ void insert_cand(float k, int m, float& tk, int& ti,
                                            float& thr, int& minl, int lane) {
    unsigned bal = __ballot_sync(0xffffffffu, k > thr);
    while (bal) {
        int src = __ffs(bal) - 1;
        bal &= bal - 1;
        float ck = __shfl_sync(0xffffffffu, k, src);
        int   cm = __shfl_sync(0xffffffffu, m, src);
        if (ck > thr) {                  // re-check: thr may have risen
            if (lane == minl) { tk = ck; ti = cm; }
            float mv = (lane < KNN) ? tk : 3.4e38f;
            int   ml = lane;
#pragma unroll
            for (int off = 16; off; off >>= 1) {
                float ov = __shfl_xor_sync(0xffffffffu, mv, off);
                int   ol = __shfl_xor_sync(0xffffffffu, ml, off);
                if (ov < mv || (ov == mv && ol < ml)) { mv = ov; ml = ol; }
            }
            thr = mv; minl = ml;         // uniform across warp
        }
    }
}

extern __shared__ float sm[];

__global__ __launch_bounds__(256, 2) void k_knn(const float* __restrict__ x) {
    float* qs   = sm + SM_QS;
    float* Bs   = sm + SM_BS;
    float* keys = sm + SM_KEYS;
    float* nsq  = sm + SM_NSQ;

    const int b  = blockIdx.y;
    const int q0 = blockIdx.x * QT;
    const int tid  = threadIdx.x;
    const int lane = tid & 31, warp = tid >> 5;   // 8 warps, 8 rows each
    const float* xb = x + (size_t)b * CDIM * NPTS;

    // ---- prologue: load query tile [c][q] ----
    for (int i = tid; i < 64 * 64; i += 256) {
        int c = i >> 6, q = i & 63;
        qs[i] = xb[c * NPTS + q0 + q];
    }

    float tk[8], thr[8];
    int   ti[8], minl[8];
#pragma unroll
    for (int r = 0; r < 8; ++r) {
        tk[r] = -3.4e38f; ti[r] = 0; thr[r] = -3.4e38f; minl[r] = 0;
    }

    const uint32_t smb = smem_u32(sm);
    const uint32_t aAddr = smb + (SM_QS + warp * 8) * 4;          // + c*256B (uniform!)
    const uint32_t bAddr = smb + (SM_BS + 2 * lane) * 4;          // + c*256B

    for (int t = 0; t < NPTS / 64; ++t) {
        const int m0 = t * 64;
        __syncthreads();   // [1] Bs(t-1) fully consumed; keys(t-1) written

        // ---- load this tile's B + negsq (LDG latency overlaps selection)
#pragma unroll
        for (int s = 0; s < 4; ++s) {
            int i4 = tid + s * 256;                 // 1024 float4 tasks
            int c = i4 >> 4, mm = (i4 & 15) * 4;
            *(float4*)&Bs[c * 64 + mm] = *(const float4*)&xb[c * NPTS + m0 + mm];
        }
        if (tid < 64) nsq[tid] = g_sq[b * NPTS + m0 + tid];

        // ---- selection for PREVIOUS tile (warp-private keys rows) ----
        if (t > 0) {
            const int mp = m0 - 64;
#pragma unroll
            for (int r = 0; r < 8; ++r) {
                const float* krow = &keys[(warp * 8 + r) * KPAD];
                float k0 = krow[lane];
                float k1 = krow[32 + lane];
                insert_cand(k0, mp + lane,      tk[r], ti[r], thr[r], minl[r], lane);
                insert_cand(k1, mp + 32 + lane, tk[r], ti[r], thr[r], minl[r], lane);
            }
        }
        __syncthreads();   // [2] Bs/nsq visible

        // ---- broadcast-A FFMA2 loop: 8 rows x 2 cols per thread ----
        unsigned long long acc[4][2];
#pragma unroll
        for (int i = 0; i < 4; ++i) { acc[i][0] = 0ull; acc[i][1] = 0ull; }

#pragma unroll 8
        for (int c = 0; c < 64; ++c) {
            ulonglong2 A0, A1;   // rows 8w..8w+3, 8w+4..8w+7 (packed pairs)
            asm volatile("ld.shared.v2.u64 {%0,%1}, [%2];"
                         : "=l"(A0.x), "=l"(A0.y) : "r"(aAddr + c * 256));
            asm volatile("ld.shared.v2.u64 {%0,%1}, [%2];"
                         : "=l"(A1.x), "=l"(A1.y) : "r"(aAddr + c * 256 + 16));
            float2 bv;
            asm volatile("ld.shared.v2.f32 {%0,%1}, [%2];"
                         : "=f"(bv.x), "=f"(bv.y) : "r"(bAddr + c * 256));
            unsigned long long d0, d1;
            DUP2(d0, bv.x); DUP2(d1, bv.y);
            FMA2(acc[0][0], A0.x, d0); FMA2(acc[0][1], A0.x, d1);
            FMA2(acc[1][0], A0.y, d0); FMA2(acc[1][1], A0.y, d1);
            FMA2(acc[2][0], A1.x, d0); FMA2(acc[2][1], A1.x, d1);
            FMA2(acc[3][0], A1.y, d0); FMA2(acc[3][1], A1.y, d1);
        }

        // ---- epilogue: keys = 2*dot + negsq -> keys smem (warp rows) ----
        {
            float n0 = nsq[2 * lane], n1 = nsq[2 * lane + 1];
#pragma unroll
            for (int rp = 0; rp < 4; ++rp) {
                float lo0, hi0, lo1, hi1;
                UNPK2(lo0, hi0, acc[rp][0]);   // col 2*lane,   rows 2rp/2rp+1
                UNPK2(lo1, hi1, acc[rp][1]);   // col 2*lane+1
                float* kr0 = &keys[(warp * 8 + 2 * rp) * KPAD + 2 * lane];
                float* kr1 = kr0 + KPAD;
                kr0[0] = fmaf(2.f, lo0, n0);
                kr0[1] = fmaf(2.f, lo1, n1);
                kr1[0] = fmaf(2.f, hi0, n0);
                kr1[1] = fmaf(2.f, hi1, n1);
            }
        }
        __syncwarp();     // keys rows visible to sibling lanes
    }

    // final tile's selection
    {
        const int mp = NPTS - 64;
#pragma unroll
        for (int r = 0; r < 8; ++r) {
            const float* krow = &keys[(warp * 8 + r) * KPAD];
            float k0 = krow[lane];
            float k1 = krow[32 + lane];
            insert_cand(k0, mp + lane,      tk[r], ti[r], thr[r], minl[r], lane);
            insert_cand(k1, mp + 32 + lane, tk[r], ti[r], thr[r], minl[r], lane);
        }
    }

    if (lane < KNN) {
#pragma unroll
        for (int r = 0; r < 8; ++r)
            g_idx[((size_t)b * NPTS + q0 + warp * 8 + r) * KNN + lane] = ti[r];
    }
}

// ---------------- kernel C: one gather pass: max/min + BN stats ----------
__global__ __launch_bounds__(256) void k_gather() {
    __shared__ int   sidx[4][KNN];
    __shared__ float red[2][4][64];
    const int o = threadIdx.x;
    const int py = threadIdx.y;
    const int tid = py * 64 + o;
    const int b = blockIdx.y;
    const int n0 = blockIdx.x * 64;
    const float* ub = g_u + (size_t)b * NPTS * OC;
    float s1 = 0.f, s2 = 0.f;

    for (int it = 0; it < 16; ++it) {
        __syncthreads();
        if (tid < 4 * KNN) {
            int g = tid / KNN, j = tid % KNN;
            sidx[g][j] = g_idx[((size_t)b * NPTS + n0 + it * 4 + g) * KNN + j];
        }
        __syncthreads();
        const int n = n0 + it * 4 + py;
        float s = 0.f, q = 0.f, mx = -3.4e38f, mn = 3.4e38f;
#pragma unroll
        for (int j = 0; j < KNN; ++j) {
            float val = ub[(size_t)sidx[py][j] * OC + o];
            s += val; q += val * val;
            mx = fmaxf(mx, val); mn = fminf(mn, val);
        }
        const size_t off = ((size_t)b * NPTS + n) * OC + o;
        float vv = g_v[off];
        g_mxv[off] = mx + vv;
        g_mnv[off] = mn + vv;
        s1 += (float)KNN * vv + s;
        s2 += (float)KNN * vv * vv + 2.f * vv * s + q;
    }
    red[0][py][o] = s1;
    red[1][py][o] = s2;
    __syncthreads();
    if (py == 0) {
        float a = red[0][0][o] + red[0][1][o] + red[0][2][o] + red[0][3][o];
        float c = red[1][0][o] + red[1][1][o] + red[1][2][o] + red[1][3][o];
        atomicAdd(&g_S1[o], a);
        atomicAdd(&g_S2[o], c);
    }
}

// ---------------- kernel D: finalize BN affine coefficients --------------
__global__ void k_finalize(const float* __restrict__ gamma,
                           const float* __restrict__ beta) {
    int o = threadIdx.x;
    const float M = (float)BSZ * (float)NPTS * (float)KNN;
    float mean = g_S1[o] / M;
    float var  = g_S2[o] / M - mean * mean;
    float a = gamma[o] * rsqrtf(var + 1e-5f);
    g_ga[o] = a;
    g_gb[o] = beta[o] - mean * a;
}

// ---------------- kernel E: affine + LeakyReLU + transpose to [b][o][n] --
__global__ __launch_bounds__(256) void k_out(float* __restrict__ out) {
    __shared__ float tile[64][65];
    const int o = threadIdx.x, ty = threadIdx.y;
    const int b = blockIdx.y, n0 = blockIdx.x * 64;
    const float a = g_ga[o], bc = g_gb[o];
#pragma unroll
    for (int it = 0; it < 16; ++it) {
        int nl = it * 4 + ty;
        size_t off = ((size_t)b * NPTS + n0 + nl) * OC + o;
        float raw = (a >= 0.f) ? g_mxv[off] : g_mnv[off];
        float val = fmaf(a, raw, bc);
        tile[nl][o] = (val >= 0.f) ? val : 0.2f * val;
    }
    __syncthreads();
#pragma unroll
    for (int it = 0; it < 16; ++it) {
        int oo = it * 4 + ty;
        out[((size_t)b * OC + oo) * NPTS + n0 + o] = tile[o][oo];
    }
}

// ---------------- launch ----------------
extern "C" void kernel_launch(void* const* d_in, const int* in_sizes, int n_in,
                              void* d_out, int out_size) {
    const float* x     = (const float*)d_in[0];
    const float* W     = (const float*)d_in[1];
    const float* gamma = (const float*)d_in[2];
    const float* beta  = (const float*)d_in[3];
    float* out = (float*)d_out;

    cudaFuncSetAttribute(k_knn, cudaFuncAttributeMaxDynamicSharedMemorySize,
                         SM_BYTES);

    k_sq      <<<dim3(NPTS / 256, BSZ), 256>>>(x);
    k_uv      <<<dim3(NPTS / 32,  BSZ), dim3(16, 16)>>>(x, W);
    k_zstat   <<<1, 64>>>();                        // pads slot 3 -> k_knn profiled
    k_knn     <<<dim3(NPTS / QT,  BSZ), 256, SM_BYTES>>>(x);
    k_gather  <<<dim3(NPTS / 64,  BSZ), dim3(64, 4)>>>();
    k_finalize<<<1, 64>>>(gamma, beta);
    k_out     <<<dim3(NPTS / 64,  BSZ), dim3(64, 4)>>>(out);
}